// round 15
// baseline (speedup 1.0000x reference)
#include <cuda_runtime.h>
#include <cuda_fp16.h>

#define Bz   16
#define Tz   512
#define Dz   384
#define Kz   3
#define ROWS (Bz*Tz)       // 8192
#define TM   32            // rows per block
#define BT   384           // block threads (12 warps)
#define NW   12            // warps per block
#define NLW  4             // n-tiles per warp (12*4 = 48 = NT)
#define NK16 (Kz*24)       // 72 k-steps of 16
#define NT   48            // n-tiles of 8 (384/8)
#define PS   196           // patch stride in u32 pairs (196%32==4 -> conflict-free frags)
#define SSTR 388           // C-stash stride in floats
#define WSCL 64.0f         // weight pre-scale (power of 2; undone in epilogue)

// ---------------- scratch (device globals) ----------------
__device__ uint4 g_wb1[NK16*NT*32];   // fp16 weight frags: (whi0,whi1,wlo0,wlo1), x64
__device__ uint4 g_wb2[NK16*NT*32];
__device__ float g_h1[ROWS*Dz];
__device__ float g_h2[ROWS*Dz];
__device__ int   g_cum[ROWS];

__device__ __forceinline__ unsigned pack_h2(__half e0, __half e1) {
    return ((unsigned)__half_as_ushort(e1) << 16) | (unsigned)__half_as_ushort(e0);
}

__device__ __forceinline__ void mma_f16(float* d,
    unsigned a0, unsigned a1, unsigned a2, unsigned a3,
    unsigned b0, unsigned b1)
{
    asm volatile(
        "mma.sync.aligned.m16n8k16.row.col.f32.f16.f16.f32 "
        "{%0,%1,%2,%3},{%4,%5,%6,%7},{%8,%9},{%0,%1,%2,%3};"
        : "+f"(d[0]), "+f"(d[1]), "+f"(d[2]), "+f"(d[3])
        : "r"(a0), "r"(a1), "r"(a2), "r"(a3), "r"(b0), "r"(b1));
}

// ---------------- weight prep: w[O][I][K] -> fp16 hi/lo fragment layout (x64) ----------------
// wb[(ks*NT + nt)*32 + lane]: lane tig=lane&3, gid=lane>>2; tap=ks/24, kc=ks%24
//   b0 covers k = kc*16 + 2tig, 2tig+1 ; b1 covers k+8 ; n = nt*8+gid
__global__ void prep_w_kernel(const float* __restrict__ w, int stage) {
    uint4* wb = stage ? g_wb2 : g_wb1;
    int idx = blockIdx.x * blockDim.x + threadIdx.x;
    if (idx >= NK16*NT*32) return;
    int lane = idx & 31;
    int nt   = (idx >> 5) % NT;
    int ks   = idx / (NT*32);
    int tig = lane & 3, gid = lane >> 2;
    int tap = ks / 24, kc = ks % 24;
    int n   = nt*8 + gid;
    int k0  = kc*16 + 2*tig;

    float v[4];
    v[0] = w[(size_t)n*Dz*Kz + (size_t)(k0    )*Kz + tap] * WSCL;
    v[1] = w[(size_t)n*Dz*Kz + (size_t)(k0 + 1)*Kz + tap] * WSCL;
    v[2] = w[(size_t)n*Dz*Kz + (size_t)(k0 + 8)*Kz + tap] * WSCL;
    v[3] = w[(size_t)n*Dz*Kz + (size_t)(k0 + 9)*Kz + tap] * WSCL;

    __half hi[4], lo[4];
    #pragma unroll
    for (int i = 0; i < 4; i++) {
        hi[i] = __float2half_rn(v[i]);
        lo[i] = __float2half_rn(v[i] - __half2float(hi[i]));
    }
    uint4 o;
    o.x = pack_h2(hi[0], hi[1]);   // whi0
    o.y = pack_h2(hi[2], hi[3]);   // whi1
    o.z = pack_h2(lo[0], lo[1]);   // wlo0
    o.w = pack_h2(lo[2], lo[3]);   // wlo1
    wb[idx] = o;
}

// ---------------- fused conv1d(K=3) + LN + ReLU (+ pred on stage 1), 2-term fp16 ----------------
// 12 warps; all cover the same 32 rows, each owns 32 output cols (4 n-tiles).
// kc loop unrolled x2 so ptxas hoists k+1 weight LDGs above k's HMMAs.
__global__ void __launch_bounds__(BT, 2) conv_ln_relu_mma(
    const float* __restrict__ x_in,
    const float* __restrict__ bias,
    const float* __restrict__ gamma,
    const float* __restrict__ beta,
    const float* __restrict__ wl,     // only used when pred != nullptr
    const float* __restrict__ bl,
    float* __restrict__ pred,         // nullptr on stage 0
    int stage)
{
    extern __shared__ unsigned smu[];
    unsigned* smA  = smu;                         // (TM+2)*PS fp16x2 patch
    float*    stash = (float*)smu;                // phase 2: TM x SSTR floats
    __shared__ float s_mean[TM], s_rstd[TM];

    const float* in  = stage ? g_h1  : x_in;
    const uint4* wb  = stage ? g_wb2 : g_wb1;
    float*       out = stage ? g_h2  : g_h1;

    const int tid  = threadIdx.x;
    const int warp = tid >> 5, lane = tid & 31;
    const int tig  = lane & 3, gid = lane >> 2;

    const int tilesPerB = Tz / TM;                 // 16
    const int b  = blockIdx.x / tilesPerB;
    const int t0 = (blockIdx.x % tilesPerB) * TM;
    const float* inB = in + (size_t)b * Tz * Dz;

    // ---- fill fp16 patch rows t0-1 .. t0+TM (34 rows) ----
    for (int i = tid; i < (TM+2)*(Dz/2); i += BT) {
        int pr = i / (Dz/2), pc = i % (Dz/2);
        int t = t0 + pr - 1;
        float2 v = make_float2(0.f, 0.f);
        if (t >= 0 && t < Tz) v = *(const float2*)(inB + (size_t)t*Dz + pc*2);
        smA[pr*PS + pc] = pack_h2(__float2half_rn(v.x), __float2half_rn(v.y));
    }
    __syncthreads();

    // ---- GEMM: warp covers 32 rows x 32 cols, 2 terms per (mt,nl) ----
    float acc[2][NLW][4];
    #pragma unroll
    for (int mt = 0; mt < 2; mt++)
        #pragma unroll
        for (int nl = 0; nl < NLW; nl++)
            #pragma unroll
            for (int e = 0; e < 4; e++) acc[mt][nl][e] = 0.f;

    #pragma unroll 1
    for (int tap = 0; tap < Kz; tap++) {
        #pragma unroll 2
        for (int kc = 0; kc < 24; kc++) {
            const int ks = tap*24 + kc;
            const int p0 = kc*8 + tig;            // fp16-pair index within row

            // A fragments, conflict-free: (row*PS + p0) distinct mod 32
            unsigned af[2][4];
            #pragma unroll
            for (int mt = 0; mt < 2; mt++) {
                int r0 = (mt*16 + gid + tap) * PS;
                int r1 = r0 + 8*PS;
                af[mt][0] = smA[r0 + p0];
                af[mt][1] = smA[r1 + p0];
                af[mt][2] = smA[r0 + p0 + 4];
                af[mt][3] = smA[r1 + p0 + 4];
            }

            const uint4* wfk = wb + ((size_t)ks*NT + warp*NLW)*32 + lane;
            #pragma unroll
            for (int nl = 0; nl < NLW; nl++) {
                uint4 wv = wfk[nl*32];
                #pragma unroll
                for (int mt = 0; mt < 2; mt++) {
                    mma_f16(acc[mt][nl], af[mt][0], af[mt][1], af[mt][2], af[mt][3], wv.x, wv.y);
                    mma_f16(acc[mt][nl], af[mt][0], af[mt][1], af[mt][2], af[mt][3], wv.z, wv.w);
                }
            }
        }
    }

    // ---- stash C (scale-undo + bias) into smem (reuse patch region) ----
    __syncthreads();
    const float inv = 1.0f / WSCL;
    #pragma unroll
    for (int mt = 0; mt < 2; mt++) {
        int r0 = mt*16 + gid;
        #pragma unroll
        for (int nl = 0; nl < NLW; nl++) {
            int c = warp*32 + nl*8 + tig*2;
            float bv0 = __ldg(bias + c), bv1 = __ldg(bias + c + 1);
            stash[r0*SSTR + c]       = acc[mt][nl][0]*inv + bv0;
            stash[r0*SSTR + c + 1]   = acc[mt][nl][1]*inv + bv1;
            stash[(r0+8)*SSTR + c]   = acc[mt][nl][2]*inv + bv0;
            stash[(r0+8)*SSTR + c+1] = acc[mt][nl][3]*inv + bv1;
        }
    }
    __syncthreads();

    // ---- per-row LN stats: warp w handles rows w, w+12, w+24 ----
    for (int r = warp; r < TM; r += NW) {
        const float* row = stash + r*SSTR;
        float s = 0.f, sq = 0.f;
        #pragma unroll
        for (int i = lane; i < Dz; i += 32) {
            float v = row[i];
            s += v; sq += v*v;
        }
        #pragma unroll
        for (int off = 16; off > 0; off >>= 1) {
            s  += __shfl_xor_sync(0xffffffffu, s,  off);
            sq += __shfl_xor_sync(0xffffffffu, sq, off);
        }
        if (lane == 0) {
            float m = s * (1.f/Dz);
            float var = sq * (1.f/Dz) - m*m;
            s_mean[r] = m;
            s_rstd[r] = rsqrtf(var + 1e-5f);
        }
    }
    __syncthreads();

    // ---- normalize + ReLU + store ----
    float* outB = out + ((size_t)b*Tz + t0) * Dz;
    for (int idx = tid; idx < TM*Dz; idx += BT) {
        int r = idx / Dz, c = idx - r*Dz;
        float v = stash[r*SSTR + c];
        float o = (v - s_mean[r]) * s_rstd[r] * __ldg(gamma + c) + __ldg(beta + c);
        outB[(size_t)r*Dz + c] = fmaxf(o, 0.f);
    }

    // ---- fused pred (stage 1 only): pred[row] = relu(LN(conv)) . wl + bl ----
    if (pred != nullptr) {
        for (int r = warp; r < TM; r += NW) {
            const float* row = stash + r*SSTR;
            float m = s_mean[r], rs = s_rstd[r];
            float s = 0.f;
            #pragma unroll
            for (int i = lane; i < Dz; i += 32) {
                float o = (row[i] - m) * rs * __ldg(gamma + i) + __ldg(beta + i);
                s += fmaxf(o, 0.f) * __ldg(wl + i);
            }
            #pragma unroll
            for (int off = 16; off > 0; off >>= 1) s += __shfl_xor_sync(0xffffffffu, s, off);
            if (lane == 0) pred[(size_t)b*Tz + t0 + r] = s + __ldg(bl);
        }
    }
}

// ---------------- per-batch inclusive cumsum of durations ----------------
__global__ void scan_kernel(const int* __restrict__ dur) {
    __shared__ int s[Tz];
    int b = blockIdx.x, t = threadIdx.x;
    s[t] = dur[b*Tz + t];
    __syncthreads();
    for (int off = 1; off < Tz; off <<= 1) {
        int v = (t >= off) ? s[t - off] : 0;
        __syncthreads();
        s[t] += v;
        __syncthreads();
    }
    g_cum[b*Tz + t] = s[t];
}

// ---------------- expansion ----------------
__global__ void expand_kernel(const float* __restrict__ x,
                              float* __restrict__ out, int L)
{
    int l = blockIdx.x, b = blockIdx.y;
    const int* cb = g_cum + b*Tz;
    int total = cb[Tz - 1];
    float4* o4 = (float4*)(out + ((size_t)b*L + l) * Dz);
    int tid = threadIdx.x;                 // 96 threads x float4 = 384 floats
    if (l >= total) {
        o4[tid] = make_float4(0.f, 0.f, 0.f, 0.f);
        return;
    }
    int lo = 0, hi = Tz - 1;
    while (lo < hi) {
        int mid = (lo + hi) >> 1;
        if (cb[mid] > l) hi = mid; else lo = mid + 1;
    }
    const float4* x4 = (const float4*)(x + ((size_t)b*Tz + lo) * Dz);
    o4[tid] = x4[tid];
}

// ---------------- launch ----------------
extern "C" void kernel_launch(void* const* d_in, const int* in_sizes, int n_in,
                              void* d_out, int out_size)
{
    const float* x   = (const float*)d_in[0];
    const int*   dur = (const int*)  d_in[1];
    const float* w1  = (const float*)d_in[2];
    const float* b1  = (const float*)d_in[3];
    const float* g1  = (const float*)d_in[4];
    const float* be1 = (const float*)d_in[5];
    const float* w2  = (const float*)d_in[6];
    const float* b2  = (const float*)d_in[7];
    const float* g2  = (const float*)d_in[8];
    const float* be2 = (const float*)d_in[9];
    const float* wl  = (const float*)d_in[10];
    const float* bl  = (const float*)d_in[11];
    float* out = (float*)d_out;

    int L = (out_size - Bz*Tz) / (Bz*Dz);
    float* pred_out = out + (size_t)Bz * L * Dz;

    // smem: max(fp16 patch 26656 B, C stash 49664 B)
    int smemPatch = (TM+2) * PS * (int)sizeof(unsigned);
    int smemStash = TM * SSTR * (int)sizeof(float);
    int SMEM = smemPatch > smemStash ? smemPatch : smemStash;
    cudaFuncSetAttribute(conv_ln_relu_mma,
                         cudaFuncAttributeMaxDynamicSharedMemorySize, SMEM);

    const int WN = NK16*NT*32;
    prep_w_kernel<<<(WN + 255)/256, 256>>>(w1, 0);
    prep_w_kernel<<<(WN + 255)/256, 256>>>(w2, 1);

    conv_ln_relu_mma<<<ROWS/TM, BT, SMEM>>>(x, b1, g1, be1, wl, bl, nullptr, 0);
    conv_ln_relu_mma<<<ROWS/TM, BT, SMEM>>>(x, b2, g2, be2, wl, bl, pred_out, 1);

    scan_kernel<<<Bz, Tz>>>(dur);
    expand_kernel<<<dim3(L, Bz), 96>>>(x, out, L);
}

// round 16
// speedup vs baseline: 1.3648x; 1.3648x over previous
#include <cuda_runtime.h>
#include <cuda_fp16.h>

#define Bz   16
#define Tz   512
#define Dz   384
#define Kz   3
#define ROWS (Bz*Tz)       // 8192
#define TM   32            // rows per block
#define BT   384           // block threads (12 warps)
#define NW   12            // warps per block
#define NLW  4             // n-tiles per warp (12*4 = 48 = NT)
#define NK16 (Kz*24)       // 72 k-steps of 16
#define NT   48            // n-tiles of 8 (384/8)
#define PS   196           // patch stride in u32 pairs (196%32==4 -> conflict-free frags)
#define SSTR 388           // C-stash stride in floats
#define WSCL 64.0f         // weight pre-scale (power of 2; undone in epilogue)

// ---------------- scratch (device globals) ----------------
// single-fp16 weight frags, two n-tiles packed per uint4:
// wb[(ks*(NT/2) + np)*32 + lane] = (b0_ntA, b1_ntA, b0_ntB, b1_ntB)
__device__ uint4 g_wb1[NK16*(NT/2)*32];
__device__ uint4 g_wb2[NK16*(NT/2)*32];
__device__ float g_h1[ROWS*Dz];
__device__ float g_h2[ROWS*Dz];
__device__ int   g_cum[ROWS];

__device__ __forceinline__ unsigned pack_h2(__half e0, __half e1) {
    return ((unsigned)__half_as_ushort(e1) << 16) | (unsigned)__half_as_ushort(e0);
}

__device__ __forceinline__ void mma_f16(float* d,
    unsigned a0, unsigned a1, unsigned a2, unsigned a3,
    unsigned b0, unsigned b1)
{
    asm volatile(
        "mma.sync.aligned.m16n8k16.row.col.f32.f16.f16.f32 "
        "{%0,%1,%2,%3},{%4,%5,%6,%7},{%8,%9},{%0,%1,%2,%3};"
        : "+f"(d[0]), "+f"(d[1]), "+f"(d[2]), "+f"(d[3])
        : "r"(a0), "r"(a1), "r"(a2), "r"(a3), "r"(b0), "r"(b1));
}

// ---------------- weight prep: w[O][I][K] -> single-fp16 fragment layout (x64) ----------------
// idx over NK16*(NT/2)*32. For pair np: ntA = 2*np, ntB = 2*np+1.
// lane tig=lane&3, gid=lane>>2; tap=ks/24, kc=ks%24; k0 = kc*16+2*tig.
__global__ void prep_w_kernel(const float* __restrict__ w, int stage) {
    uint4* wb = stage ? g_wb2 : g_wb1;
    int idx = blockIdx.x * blockDim.x + threadIdx.x;
    if (idx >= NK16*(NT/2)*32) return;
    int lane = idx & 31;
    int np   = (idx >> 5) % (NT/2);
    int ks   = idx / ((NT/2)*32);
    int tig = lane & 3, gid = lane >> 2;
    int tap = ks / 24, kc = ks % 24;
    int k0  = kc*16 + 2*tig;
    int nA  = (2*np)*8 + gid;
    int nB  = (2*np + 1)*8 + gid;

    float vA0 = w[(size_t)nA*Dz*Kz + (size_t)(k0    )*Kz + tap] * WSCL;
    float vA1 = w[(size_t)nA*Dz*Kz + (size_t)(k0 + 1)*Kz + tap] * WSCL;
    float vA2 = w[(size_t)nA*Dz*Kz + (size_t)(k0 + 8)*Kz + tap] * WSCL;
    float vA3 = w[(size_t)nA*Dz*Kz + (size_t)(k0 + 9)*Kz + tap] * WSCL;
    float vB0 = w[(size_t)nB*Dz*Kz + (size_t)(k0    )*Kz + tap] * WSCL;
    float vB1 = w[(size_t)nB*Dz*Kz + (size_t)(k0 + 1)*Kz + tap] * WSCL;
    float vB2 = w[(size_t)nB*Dz*Kz + (size_t)(k0 + 8)*Kz + tap] * WSCL;
    float vB3 = w[(size_t)nB*Dz*Kz + (size_t)(k0 + 9)*Kz + tap] * WSCL;

    uint4 o;
    o.x = pack_h2(__float2half_rn(vA0), __float2half_rn(vA1));  // b0 ntA
    o.y = pack_h2(__float2half_rn(vA2), __float2half_rn(vA3));  // b1 ntA
    o.z = pack_h2(__float2half_rn(vB0), __float2half_rn(vB1));  // b0 ntB
    o.w = pack_h2(__float2half_rn(vB2), __float2half_rn(vB3));  // b1 ntB
    wb[idx] = o;
}

// ---------------- fused conv1d(K=3) + LN + ReLU (+ pred on stage 1), 1-term fp16 ----------------
// 12 warps; all cover the same 32 rows, each owns 32 output cols (4 n-tiles).
__global__ void __launch_bounds__(BT, 2) conv_ln_relu_mma(
    const float* __restrict__ x_in,
    const float* __restrict__ bias,
    const float* __restrict__ gamma,
    const float* __restrict__ beta,
    const float* __restrict__ wl,     // only used when pred != nullptr
    const float* __restrict__ bl,
    float* __restrict__ pred,         // nullptr on stage 0
    int stage)
{
    extern __shared__ unsigned smu[];
    unsigned* smA  = smu;                         // (TM+2)*PS fp16x2 patch
    float*    stash = (float*)smu;                // phase 2: TM x SSTR floats
    __shared__ float s_mean[TM], s_rstd[TM];

    const float* in  = stage ? g_h1  : x_in;
    const uint4* wb  = stage ? g_wb2 : g_wb1;
    float*       out = stage ? g_h2  : g_h1;

    const int tid  = threadIdx.x;
    const int warp = tid >> 5, lane = tid & 31;
    const int tig  = lane & 3, gid = lane >> 2;

    const int tilesPerB = Tz / TM;                 // 16
    const int b  = blockIdx.x / tilesPerB;
    const int t0 = (blockIdx.x % tilesPerB) * TM;
    const float* inB = in + (size_t)b * Tz * Dz;

    // ---- fill fp16 patch rows t0-1 .. t0+TM (34 rows) ----
    for (int i = tid; i < (TM+2)*(Dz/2); i += BT) {
        int pr = i / (Dz/2), pc = i % (Dz/2);
        int t = t0 + pr - 1;
        float2 v = make_float2(0.f, 0.f);
        if (t >= 0 && t < Tz) v = *(const float2*)(inB + (size_t)t*Dz + pc*2);
        smA[pr*PS + pc] = pack_h2(__float2half_rn(v.x), __float2half_rn(v.y));
    }
    __syncthreads();

    // ---- GEMM: warp covers 32 rows x 32 cols, 1 term per (mt,nl) ----
    float acc[2][NLW][4];
    #pragma unroll
    for (int mt = 0; mt < 2; mt++)
        #pragma unroll
        for (int nl = 0; nl < NLW; nl++)
            #pragma unroll
            for (int e = 0; e < 4; e++) acc[mt][nl][e] = 0.f;

    #pragma unroll 1
    for (int tap = 0; tap < Kz; tap++) {
        #pragma unroll 2
        for (int kc = 0; kc < 24; kc++) {
            const int ks = tap*24 + kc;
            const int p0 = kc*8 + tig;            // fp16-pair index within row

            // A fragments, conflict-free: (row*PS + p0) distinct mod 32
            unsigned af[2][4];
            #pragma unroll
            for (int mt = 0; mt < 2; mt++) {
                int r0 = (mt*16 + gid + tap) * PS;
                int r1 = r0 + 8*PS;
                af[mt][0] = smA[r0 + p0];
                af[mt][1] = smA[r1 + p0];
                af[mt][2] = smA[r0 + p0 + 4];
                af[mt][3] = smA[r1 + p0 + 4];
            }

            const uint4* wfk = wb + ((size_t)ks*(NT/2) + warp*2)*32 + lane;
            #pragma unroll
            for (int np = 0; np < 2; np++) {
                uint4 wv = wfk[np*32];
                #pragma unroll
                for (int mt = 0; mt < 2; mt++) {
                    mma_f16(acc[mt][np*2],     af[mt][0], af[mt][1], af[mt][2], af[mt][3], wv.x, wv.y);
                    mma_f16(acc[mt][np*2 + 1], af[mt][0], af[mt][1], af[mt][2], af[mt][3], wv.z, wv.w);
                }
            }
        }
    }

    // ---- stash C (scale-undo + bias) into smem (reuse patch region) ----
    __syncthreads();
    const float inv = 1.0f / WSCL;
    #pragma unroll
    for (int mt = 0; mt < 2; mt++) {
        int r0 = mt*16 + gid;
        #pragma unroll
        for (int nl = 0; nl < NLW; nl++) {
            int c = warp*32 + nl*8 + tig*2;
            float bv0 = __ldg(bias + c), bv1 = __ldg(bias + c + 1);
            stash[r0*SSTR + c]       = acc[mt][nl][0]*inv + bv0;
            stash[r0*SSTR + c + 1]   = acc[mt][nl][1]*inv + bv1;
            stash[(r0+8)*SSTR + c]   = acc[mt][nl][2]*inv + bv0;
            stash[(r0+8)*SSTR + c+1] = acc[mt][nl][3]*inv + bv1;
        }
    }
    __syncthreads();

    // ---- per-row LN stats: warp w handles rows w, w+12, w+24 ----
    for (int r = warp; r < TM; r += NW) {
        const float* row = stash + r*SSTR;
        float s = 0.f, sq = 0.f;
        #pragma unroll
        for (int i = lane; i < Dz; i += 32) {
            float v = row[i];
            s += v; sq += v*v;
        }
        #pragma unroll
        for (int off = 16; off > 0; off >>= 1) {
            s  += __shfl_xor_sync(0xffffffffu, s,  off);
            sq += __shfl_xor_sync(0xffffffffu, sq, off);
        }
        if (lane == 0) {
            float m = s * (1.f/Dz);
            float var = sq * (1.f/Dz) - m*m;
            s_mean[r] = m;
            s_rstd[r] = rsqrtf(var + 1e-5f);
        }
    }
    __syncthreads();

    // ---- normalize + ReLU + store ----
    float* outB = out + ((size_t)b*Tz + t0) * Dz;
    for (int idx = tid; idx < TM*Dz; idx += BT) {
        int r = idx / Dz, c = idx - r*Dz;
        float v = stash[r*SSTR + c];
        float o = (v - s_mean[r]) * s_rstd[r] * __ldg(gamma + c) + __ldg(beta + c);
        outB[(size_t)r*Dz + c] = fmaxf(o, 0.f);
    }

    // ---- fused pred (stage 1 only): pred[row] = relu(LN(conv)) . wl + bl ----
    if (pred != nullptr) {
        for (int r = warp; r < TM; r += NW) {
            const float* row = stash + r*SSTR;
            float m = s_mean[r], rs = s_rstd[r];
            float s = 0.f;
            #pragma unroll
            for (int i = lane; i < Dz; i += 32) {
                float o = (row[i] - m) * rs * __ldg(gamma + i) + __ldg(beta + i);
                s += fmaxf(o, 0.f) * __ldg(wl + i);
            }
            #pragma unroll
            for (int off = 16; off > 0; off >>= 1) s += __shfl_xor_sync(0xffffffffu, s, off);
            if (lane == 0) pred[(size_t)b*Tz + t0 + r] = s + __ldg(bl);
        }
    }
}

// ---------------- per-batch inclusive cumsum of durations ----------------
__global__ void scan_kernel(const int* __restrict__ dur) {
    __shared__ int s[Tz];
    int b = blockIdx.x, t = threadIdx.x;
    s[t] = dur[b*Tz + t];
    __syncthreads();
    for (int off = 1; off < Tz; off <<= 1) {
        int v = (t >= off) ? s[t - off] : 0;
        __syncthreads();
        s[t] += v;
        __syncthreads();
    }
    g_cum[b*Tz + t] = s[t];
}

// ---------------- expansion ----------------
__global__ void expand_kernel(const float* __restrict__ x,
                              float* __restrict__ out, int L)
{
    int l = blockIdx.x, b = blockIdx.y;
    const int* cb = g_cum + b*Tz;
    int total = cb[Tz - 1];
    float4* o4 = (float4*)(out + ((size_t)b*L + l) * Dz);
    int tid = threadIdx.x;                 // 96 threads x float4 = 384 floats
    if (l >= total) {
        o4[tid] = make_float4(0.f, 0.f, 0.f, 0.f);
        return;
    }
    int lo = 0, hi = Tz - 1;
    while (lo < hi) {
        int mid = (lo + hi) >> 1;
        if (cb[mid] > l) hi = mid; else lo = mid + 1;
    }
    const float4* x4 = (const float4*)(x + ((size_t)b*Tz + lo) * Dz);
    o4[tid] = x4[tid];
}

// ---------------- launch ----------------
extern "C" void kernel_launch(void* const* d_in, const int* in_sizes, int n_in,
                              void* d_out, int out_size)
{
    const float* x   = (const float*)d_in[0];
    const int*   dur = (const int*)  d_in[1];
    const float* w1  = (const float*)d_in[2];
    const float* b1  = (const float*)d_in[3];
    const float* g1  = (const float*)d_in[4];
    const float* be1 = (const float*)d_in[5];
    const float* w2  = (const float*)d_in[6];
    const float* b2  = (const float*)d_in[7];
    const float* g2  = (const float*)d_in[8];
    const float* be2 = (const float*)d_in[9];
    const float* wl  = (const float*)d_in[10];
    const float* bl  = (const float*)d_in[11];
    float* out = (float*)d_out;

    int L = (out_size - Bz*Tz) / (Bz*Dz);
    float* pred_out = out + (size_t)Bz * L * Dz;

    // smem: max(fp16 patch 26656 B, C stash 49664 B)
    int smemPatch = (TM+2) * PS * (int)sizeof(unsigned);
    int smemStash = TM * SSTR * (int)sizeof(float);
    int SMEM = smemPatch > smemStash ? smemPatch : smemStash;
    cudaFuncSetAttribute(conv_ln_relu_mma,
                         cudaFuncAttributeMaxDynamicSharedMemorySize, SMEM);

    const int WN = NK16*(NT/2)*32;
    prep_w_kernel<<<(WN + 255)/256, 256>>>(w1, 0);
    prep_w_kernel<<<(WN + 255)/256, 256>>>(w2, 1);

    conv_ln_relu_mma<<<ROWS/TM, BT, SMEM>>>(x, b1, g1, be1, wl, bl, nullptr, 0);
    conv_ln_relu_mma<<<ROWS/TM, BT, SMEM>>>(x, b2, g2, be2, wl, bl, pred_out, 1);

    scan_kernel<<<Bz, Tz>>>(dur);
    expand_kernel<<<dim3(L, Bz), 96>>>(x, out, L);
}